// round 1
// baseline (speedup 1.0000x reference)
#include <cuda_runtime.h>
#include <cstdint>
#include <cstddef>

#define NC 10
#define DD 512
#define D4 128   // DD / 4

// Scratch (no cudaMalloc allowed)
__device__ float g_sums[NC * DD];
__device__ int   g_counts[NC];
__device__ float g_proto[NC * DD];
__device__ float g_sqp[NC];
__device__ float g_loss;

// Packed f32x2 FMA (Blackwell): d = a*b + c elementwise on two packed floats.
static __device__ __forceinline__ unsigned long long fma2(unsigned long long a,
                                                          unsigned long long b,
                                                          unsigned long long c) {
    unsigned long long d;
    asm("fma.rn.f32x2 %0, %1, %2, %3;" : "=l"(d) : "l"(a), "l"(b), "l"(c));
    return d;
}
static __device__ __forceinline__ float u64_sum2(unsigned long long v) {
    float lo, hi;
    asm("mov.b64 {%0,%1}, %2;" : "=f"(lo), "=f"(hi) : "l"(v));
    return lo + hi;
}

// ---------------------------------------------------------------------------
// K0: zero accumulators (fresh every graph replay)
// ---------------------------------------------------------------------------
__global__ void k_zero() {
    int i = blockIdx.x * blockDim.x + threadIdx.x;
    if (i < NC * DD) g_sums[i] = 0.0f;
    if (i < NC)      g_counts[i] = 0;
    if (i == 0)      g_loss = 0.0f;
}

// ---------------------------------------------------------------------------
// K1: segment sums + counts.
// 256 threads = 2 row-groups of 128. Each thread owns one float4 column slot
// in its group's smem replica -> no races, no smem atomics.
// ---------------------------------------------------------------------------
__global__ __launch_bounds__(256) void k_segsum(const float4* __restrict__ E4,
                                                const int* __restrict__ labels,
                                                int nrows) {
    __shared__ float4 s[2][NC][D4];   // 40 KB
    const int g = threadIdx.x >> 7;       // row-group 0/1
    const int t = threadIdx.x & 127;      // float4 column

#pragma unroll
    for (int c = 0; c < NC; c++) s[g][c][t] = make_float4(0.f, 0.f, 0.f, 0.f);
    __syncthreads();

    int cnt[NC];
#pragma unroll
    for (int c = 0; c < NC; c++) cnt[c] = 0;

    const long stride = (long)gridDim.x * 8;
    for (long r0 = (long)blockIdx.x * 8 + g * 4; r0 < nrows; r0 += stride) {
        int   lab[4];
        float4 v[4];
#pragma unroll
        for (int j = 0; j < 4; j++) {
            lab[j] = labels[r0 + j];
            v[j]   = E4[(size_t)(r0 + j) * D4 + t];
        }
#pragma unroll
        for (int j = 0; j < 4; j++) {
            float4* sp = &s[g][lab[j]][t];
            float4  a  = *sp;
            a.x += v[j].x; a.y += v[j].y; a.z += v[j].z; a.w += v[j].w;
            *sp = a;
        }
        if (t == 0) {
#pragma unroll
            for (int j = 0; j < 4; j++)
#pragma unroll
                for (int c = 0; c < NC; c++) cnt[c] += (lab[j] == c);
        }
    }
    __syncthreads();

    // Reduce the two replicas, flush to global with atomics.
    const float4* s0 = &s[0][0][0];
    for (int i = threadIdx.x; i < NC * D4; i += 256) {
        float4 a = s0[i];
        float4 b = s0[NC * D4 + i];
        a.x += b.x; a.y += b.y; a.z += b.z; a.w += b.w;
        atomicAdd(&g_sums[i * 4 + 0], a.x);
        atomicAdd(&g_sums[i * 4 + 1], a.y);
        atomicAdd(&g_sums[i * 4 + 2], a.z);
        atomicAdd(&g_sums[i * 4 + 3], a.w);
    }
    if (t == 0) {
#pragma unroll
        for (int c = 0; c < NC; c++)
            if (cnt[c]) atomicAdd(&g_counts[c], cnt[c]);
    }
}

// ---------------------------------------------------------------------------
// K2: prototypes = sums / counts ; sq_p[c] = ||p_c||^2
// ---------------------------------------------------------------------------
__global__ __launch_bounds__(512) void k_proto() {
    const int i = threadIdx.x;   // 0..511
#pragma unroll
    for (int c = 0; c < NC; c++) {
        float p = g_sums[c * DD + i] / (float)g_counts[c];
        g_proto[c * DD + i] = p;
    }
    __syncthreads();
    if (i < NC) {
        float acc = 0.f;
#pragma unroll 8
        for (int j = 0; j < DD; j++) {
            float p = g_proto[i * DD + j];
            acc = fmaf(p, p, acc);
        }
        g_sqp[i] = acc;
    }
}

// ---------------------------------------------------------------------------
// K3: logits + log-softmax + loss partials.
// One warp handles 8 rows; each 4-lane group handles one row (128 f32 each).
// Packed f32x2 FMAs keep the FMA pipe under capacity -> memory bound.
// ---------------------------------------------------------------------------
__global__ __launch_bounds__(256) void k_logits(const float4* __restrict__ E4,
                                                const int* __restrict__ labels,
                                                float* __restrict__ out,
                                                int nrows) {
    __shared__ float4 sp[NC * D4];   // 20 KB prototypes
    __shared__ float  ssqp[NC];
    __shared__ float  sloss;

    for (int i = threadIdx.x; i < NC * D4; i += 256)
        sp[i] = ((const float4*)g_proto)[i];
    if (threadIdx.x < NC) ssqp[threadIdx.x] = g_sqp[threadIdx.x];
    if (threadIdx.x == 0) sloss = 0.f;
    __syncthreads();

    const int warp = threadIdx.x >> 5;
    const int lane = threadIdx.x & 31;
    const int row  = blockIdx.x * 64 + warp * 8 + (lane >> 2);
    const int cg   = lane & 3;
    const bool valid = (row < nrows);
    const int rowc = valid ? row : 0;

    const ulonglong2* __restrict__ Ep =
        (const ulonglong2*)E4 + (size_t)rowc * D4;
    const ulonglong2* __restrict__ Pp = (const ulonglong2*)sp;

    unsigned long long dot[NC];
#pragma unroll
    for (int c = 0; c < NC; c++) dot[c] = 0ull;
    unsigned long long sq = 0ull;

#pragma unroll 4
    for (int k = 0; k < 32; k++) {
        const int idx = k * 4 + cg;
        ulonglong2 v = Ep[idx];
        sq = fma2(v.x, v.x, sq);
        sq = fma2(v.y, v.y, sq);
#pragma unroll
        for (int c = 0; c < NC; c++) {
            ulonglong2 p = Pp[c * D4 + idx];
            dot[c] = fma2(v.x, p.x, dot[c]);
            dot[c] = fma2(v.y, p.y, dot[c]);
        }
    }

    // Reduce across the 4-lane group (all 4 lanes end with full sums).
    float sq_e = u64_sum2(sq);
    sq_e += __shfl_xor_sync(0xFFFFFFFFu, sq_e, 1);
    sq_e += __shfl_xor_sync(0xFFFFFFFFu, sq_e, 2);

    const int lab = valid ? labels[rowc] : 0;
    float l[NC];
    float m = -1e30f, lsel = 0.f;
#pragma unroll
    for (int c = 0; c < NC; c++) {
        float d = u64_sum2(dot[c]);
        d += __shfl_xor_sync(0xFFFFFFFFu, d, 1);
        d += __shfl_xor_sync(0xFFFFFFFFu, d, 2);
        float d2 = sq_e + ssqp[c] - 2.0f * d;
        float lg = -fmaxf(d2, 0.0f);
        l[c] = lg;
        m = fmaxf(m, lg);
        if (c == lab) lsel = lg;
    }

    float se = 0.f;
#pragma unroll
    for (int c = 0; c < NC; c++) se += __expf(l[c] - m);

    if (cg == 0 && valid) {
        float* o = out + 1 + (size_t)row * NC;
#pragma unroll
        for (int c = 0; c < NC; c++) o[c] = l[c];
    }

    float lv = (cg == 0 && valid) ? (m + __logf(se) - lsel) : 0.f;
#pragma unroll
    for (int st = 16; st >= 1; st >>= 1)
        lv += __shfl_xor_sync(0xFFFFFFFFu, lv, st);
    if (lane == 0) atomicAdd(&sloss, lv);
    __syncthreads();
    if (threadIdx.x == 0) atomicAdd(&g_loss, sloss);
}

// ---------------------------------------------------------------------------
// K4: finalize loss
// ---------------------------------------------------------------------------
__global__ void k_final(float* __restrict__ out, int nrows) {
    out[0] = g_loss * (1.0f / (float)nrows);
}

extern "C" void kernel_launch(void* const* d_in, const int* in_sizes, int n_in,
                              void* d_out, int out_size) {
    const float* E      = (const float*)d_in[0];
    const int*   labels = (const int*)d_in[1];
    float*       out    = (float*)d_out;
    const int nrows = in_sizes[1];   // 131072

    k_zero<<<20, 256>>>();
    k_segsum<<<296, 256>>>((const float4*)E, labels, nrows);
    k_proto<<<1, 512>>>();
    k_logits<<<(nrows + 63) / 64, 256>>>((const float4*)E, labels, out, nrows);
    k_final<<<1, 1>>>(out, nrows);
}

// round 2
// speedup vs baseline: 1.1029x; 1.1029x over previous
#include <cuda_runtime.h>
#include <cstdint>
#include <cstddef>

#define NC 10
#define DD 512
#define D4 128   // DD / 4 (float4 / ulonglong2 units per row)

typedef unsigned long long ull;

// Scratch (no cudaMalloc allowed)
__device__ float  g_sums[NC * DD];
__device__ int    g_counts[NC];
__device__ float4 g_proto4[NC * D4];
__device__ float  g_sqp[NC];
__device__ float  g_loss;

// Packed f32x2 FMA (Blackwell): elementwise d = a*b + c on two packed floats.
static __device__ __forceinline__ ull fma2(ull a, ull b, ull c) {
    ull d;
    asm("fma.rn.f32x2 %0, %1, %2, %3;" : "=l"(d) : "l"(a), "l"(b), "l"(c));
    return d;
}
static __device__ __forceinline__ float u64_sum2(ull v) {
    float lo, hi;
    asm("mov.b64 {%0,%1}, %2;" : "=f"(lo), "=f"(hi) : "l"(v));
    return lo + hi;
}

// ---------------------------------------------------------------------------
// K0: zero accumulators (fresh every graph replay)
// ---------------------------------------------------------------------------
__global__ void k_zero() {
    int i = blockIdx.x * blockDim.x + threadIdx.x;
    if (i < NC * DD) g_sums[i] = 0.0f;
    if (i < NC)      g_counts[i] = 0;
    if (i == 0)      g_loss = 0.0f;
}

// ---------------------------------------------------------------------------
// K1: segment sums + counts.
// 256 threads = 2 row-groups of 128; thread owns one float4 column slot in its
// group's smem replica (no races). 40KB smem -> 5 blocks/SM, grid 740.
// ---------------------------------------------------------------------------
__global__ __launch_bounds__(256) void k_segsum(const float4* __restrict__ E4,
                                                const int* __restrict__ labels,
                                                int nrows) {
    __shared__ float4 s[2][NC][D4];   // 40 KB
    __shared__ int scnt[NC];
    const int g = threadIdx.x >> 7;       // row-group 0/1
    const int t = threadIdx.x & 127;      // float4 column

    if (threadIdx.x < NC) scnt[threadIdx.x] = 0;
#pragma unroll
    for (int c = 0; c < NC; c++) s[g][c][t] = make_float4(0.f, 0.f, 0.f, 0.f);
    __syncthreads();

    const long stride = (long)gridDim.x * 8;
    for (long r0 = (long)blockIdx.x * 8 + g * 4; r0 < nrows; r0 += stride) {
        if (r0 + 3 < nrows) {
            const int4 lab4 = *(const int4*)(labels + r0);
            int lab[4] = {lab4.x, lab4.y, lab4.z, lab4.w};
            float4 v[4];
#pragma unroll
            for (int j = 0; j < 4; j++)
                v[j] = E4[(size_t)(r0 + j) * D4 + t];
            if (t == 0) {
#pragma unroll
                for (int j = 0; j < 4; j++) atomicAdd(&scnt[lab[j]], 1);
            }
#pragma unroll
            for (int j = 0; j < 4; j++) {
                float4* sp = &s[g][lab[j]][t];
                float4  a  = *sp;
                a.x += v[j].x; a.y += v[j].y; a.z += v[j].z; a.w += v[j].w;
                *sp = a;
            }
        } else {
            for (int j = 0; j < 4 && r0 + j < nrows; j++) {
                int lj = labels[r0 + j];
                float4 v = E4[(size_t)(r0 + j) * D4 + t];
                if (t == 0) atomicAdd(&scnt[lj], 1);
                float4* sp = &s[g][lj][t];
                float4  a  = *sp;
                a.x += v.x; a.y += v.y; a.z += v.z; a.w += v.w;
                *sp = a;
            }
        }
    }
    __syncthreads();

    // Reduce the two replicas, flush to global with atomics.
    const float4* s0 = &s[0][0][0];
    for (int i = threadIdx.x; i < NC * D4; i += 256) {
        float4 a = s0[i];
        float4 b = s0[NC * D4 + i];
        a.x += b.x; a.y += b.y; a.z += b.z; a.w += b.w;
        atomicAdd(&g_sums[i * 4 + 0], a.x);
        atomicAdd(&g_sums[i * 4 + 1], a.y);
        atomicAdd(&g_sums[i * 4 + 2], a.z);
        atomicAdd(&g_sums[i * 4 + 3], a.w);
    }
    if (threadIdx.x < NC && scnt[threadIdx.x])
        atomicAdd(&g_counts[threadIdx.x], scnt[threadIdx.x]);
}

// ---------------------------------------------------------------------------
// K2: prototypes = sums / counts ; sq_p[c] = ||p_c||^2 (warp per class)
// ---------------------------------------------------------------------------
__global__ __launch_bounds__(512) void k_proto() {
    const int i = threadIdx.x;   // 0..511
#pragma unroll
    for (int c = 0; c < NC; c++)
        ((float*)g_proto4)[c * DD + i] = g_sums[c * DD + i] / (float)g_counts[c];
    __syncthreads();
    const int c    = i >> 5;
    const int lane = i & 31;
    if (c < NC) {
        const float* p = (const float*)g_proto4 + c * DD;
        float acc = 0.f;
        for (int j = lane; j < DD; j += 32) acc = fmaf(p[j], p[j], acc);
#pragma unroll
        for (int st = 16; st >= 1; st >>= 1)
            acc += __shfl_xor_sync(0xFFFFFFFFu, acc, st);
        if (lane == 0) g_sqp[c] = acc;
    }
}

// ---------------------------------------------------------------------------
// K3 helpers
// ---------------------------------------------------------------------------
// Finish one row: dotf[c] and sqf are this lane's partial sums; the other 3
// lanes of the 4-lane group hold the rest. Returns the row's NLL on cg==0.
static __device__ __forceinline__ float row_epi(const float* dotf, float sqf,
                                                int row, int lab,
                                                const float* __restrict__ ssqp,
                                                float* __restrict__ out, int cg) {
    float sqe = sqf;
    sqe += __shfl_xor_sync(0xFFFFFFFFu, sqe, 1);
    sqe += __shfl_xor_sync(0xFFFFFFFFu, sqe, 2);
    float l[NC];
    float m = -1e30f, lsel = 0.f;
#pragma unroll
    for (int c = 0; c < NC; c++) {
        float d = dotf[c];
        d += __shfl_xor_sync(0xFFFFFFFFu, d, 1);
        d += __shfl_xor_sync(0xFFFFFFFFu, d, 2);
        float d2 = sqe + ssqp[c] - 2.0f * d;
        float lg = -fmaxf(d2, 0.0f);
        l[c] = lg;
        m = fmaxf(m, lg);
        if (c == lab) lsel = lg;
    }
    float se = 0.f;
#pragma unroll
    for (int c = 0; c < NC; c++) se += __expf(l[c] - m);
    if (cg == 0) {
        float* o = out + 1 + (size_t)row * NC;
#pragma unroll
        for (int c = 0; c < NC; c++) o[c] = l[c];
    }
    return (cg == 0) ? (m + __logf(se) - lsel) : 0.f;
}

// Slow scalar path for tail rows.
static __device__ __forceinline__ float row_scalar(const float4* __restrict__ E4,
                                                   const float4* __restrict__ sp,
                                                   const float* __restrict__ ssqp,
                                                   const int* __restrict__ labels,
                                                   float* __restrict__ out,
                                                   int row, int cg) {
    float dot[NC];
#pragma unroll
    for (int c = 0; c < NC; c++) dot[c] = 0.f;
    float sqf = 0.f;
    for (int t = cg; t < D4; t += 4) {
        float4 e = E4[(size_t)row * D4 + t];
        sqf += e.x * e.x + e.y * e.y + e.z * e.z + e.w * e.w;
#pragma unroll
        for (int c = 0; c < NC; c++) {
            float4 p = sp[c * D4 + t];
            dot[c] += e.x * p.x + e.y * p.y + e.z * p.z + e.w * p.w;
        }
    }
    return row_epi(dot, sqf, row, labels[row], ssqp, out, cg);
}

// ---------------------------------------------------------------------------
// K3: logits + log-softmax + loss. 128 threads; each 4-lane group owns 4 rows
// so prototype LDS traffic is amortized 4x. Packed f32x2 FMAs.
// ---------------------------------------------------------------------------
__global__ __launch_bounds__(128) void k_logits(const float4* __restrict__ E4,
                                                const int* __restrict__ labels,
                                                float* __restrict__ out,
                                                int nrows) {
    __shared__ float4 sp[NC * D4];   // 20 KB prototypes
    __shared__ float  ssqp[NC];
    __shared__ float  sloss;

    for (int i = threadIdx.x; i < NC * D4; i += 128)
        sp[i] = g_proto4[i];
    if (threadIdx.x < NC) ssqp[threadIdx.x] = g_sqp[threadIdx.x];
    if (threadIdx.x == 0) sloss = 0.f;
    __syncthreads();

    const int warp = threadIdx.x >> 5;
    const int lane = threadIdx.x & 31;
    const int cg   = lane & 3;
    const int grp  = lane >> 2;
    const int r0   = blockIdx.x * 128 + warp * 32 + grp * 4;

    float lvsum = 0.f;

    if (r0 + 3 < nrows) {
        const ulonglong2* __restrict__ Ep =
            (const ulonglong2*)E4 + (size_t)r0 * D4;
        const ulonglong2* __restrict__ Pp = (const ulonglong2*)sp;

        ull dot0[NC], dot1[NC], dot2[NC], dot3[NC];
#pragma unroll
        for (int c = 0; c < NC; c++) { dot0[c] = 0; dot1[c] = 0; dot2[c] = 0; dot3[c] = 0; }
        ull sq0 = 0, sq1 = 0, sq2 = 0, sq3 = 0;

#pragma unroll 4
        for (int k = 0; k < 32; k++) {
            const int idx = k * 4 + cg;
            ulonglong2 v0 = Ep[idx];
            ulonglong2 v1 = Ep[idx + D4];
            ulonglong2 v2 = Ep[idx + 2 * D4];
            ulonglong2 v3 = Ep[idx + 3 * D4];
            sq0 = fma2(v0.x, v0.x, sq0); sq0 = fma2(v0.y, v0.y, sq0);
            sq1 = fma2(v1.x, v1.x, sq1); sq1 = fma2(v1.y, v1.y, sq1);
            sq2 = fma2(v2.x, v2.x, sq2); sq2 = fma2(v2.y, v2.y, sq2);
            sq3 = fma2(v3.x, v3.x, sq3); sq3 = fma2(v3.y, v3.y, sq3);
#pragma unroll
            for (int c = 0; c < NC; c++) {
                ulonglong2 p = Pp[c * D4 + idx];
                dot0[c] = fma2(v0.x, p.x, dot0[c]); dot0[c] = fma2(v0.y, p.y, dot0[c]);
                dot1[c] = fma2(v1.x, p.x, dot1[c]); dot1[c] = fma2(v1.y, p.y, dot1[c]);
                dot2[c] = fma2(v2.x, p.x, dot2[c]); dot2[c] = fma2(v2.y, p.y, dot2[c]);
                dot3[c] = fma2(v3.x, p.x, dot3[c]); dot3[c] = fma2(v3.y, p.y, dot3[c]);
            }
        }

        const int4 lab4 = *(const int4*)(labels + r0);
        float df[NC];

#pragma unroll
        for (int c = 0; c < NC; c++) df[c] = u64_sum2(dot0[c]);
        lvsum += row_epi(df, u64_sum2(sq0), r0 + 0, lab4.x, ssqp, out, cg);
#pragma unroll
        for (int c = 0; c < NC; c++) df[c] = u64_sum2(dot1[c]);
        lvsum += row_epi(df, u64_sum2(sq1), r0 + 1, lab4.y, ssqp, out, cg);
#pragma unroll
        for (int c = 0; c < NC; c++) df[c] = u64_sum2(dot2[c]);
        lvsum += row_epi(df, u64_sum2(sq2), r0 + 2, lab4.z, ssqp, out, cg);
#pragma unroll
        for (int c = 0; c < NC; c++) df[c] = u64_sum2(dot3[c]);
        lvsum += row_epi(df, u64_sum2(sq3), r0 + 3, lab4.w, ssqp, out, cg);
    } else {
        for (int j = 0; j < 4; j++)
            if (r0 + j < nrows)
                lvsum += row_scalar(E4, sp, ssqp, labels, out, r0 + j, cg);
    }

#pragma unroll
    for (int st = 16; st >= 1; st >>= 1)
        lvsum += __shfl_xor_sync(0xFFFFFFFFu, lvsum, st);
    if (lane == 0) atomicAdd(&sloss, lvsum);
    __syncthreads();
    if (threadIdx.x == 0) atomicAdd(&g_loss, sloss);
}

// ---------------------------------------------------------------------------
// K4: finalize loss
// ---------------------------------------------------------------------------
__global__ void k_final(float* __restrict__ out, int nrows) {
    out[0] = g_loss * (1.0f / (float)nrows);
}

extern "C" void kernel_launch(void* const* d_in, const int* in_sizes, int n_in,
                              void* d_out, int out_size) {
    const float* E      = (const float*)d_in[0];
    const int*   labels = (const int*)d_in[1];
    float*       out    = (float*)d_out;
    const int nrows = in_sizes[1];   // 131072

    k_zero<<<20, 256>>>();
    k_segsum<<<740, 256>>>((const float4*)E, labels, nrows);
    k_proto<<<1, 512>>>();
    k_logits<<<(nrows + 127) / 128, 128>>>((const float4*)E, labels, out, nrows);
    k_final<<<1, 1>>>(out, nrows);
}

// round 4
// speedup vs baseline: 1.1959x; 1.0843x over previous
#include <cuda_runtime.h>
#include <cstdint>
#include <cstddef>

#define NC 10
#define DD 512
#define D4 128          // DD/4
#define SEG_BLOCKS 296
#define SEG_GROUPS (SEG_BLOCKS * 4)
#define SEG_SMEM (4 * NC * D4 * 16)   // 81920 bytes

typedef unsigned long long ull;

// Scratch (no cudaMalloc allowed)
__device__ float4 g_part4[SEG_BLOCKS * NC * D4];   // 6.06 MB partial sums
__device__ int    g_cnt_part[SEG_BLOCKS * NC];
__device__ float4 g_sums4[NC * D4];
__device__ float4 g_proto4[NC * D4];
__device__ float  g_sqp[NC];
__device__ float  g_loss;

// Packed f32x2 FMA (Blackwell): elementwise d = a*b + c on two packed floats.
static __device__ __forceinline__ ull fma2(ull a, ull b, ull c) {
    ull d;
    asm("fma.rn.f32x2 %0, %1, %2, %3;" : "=l"(d) : "l"(a), "l"(b), "l"(c));
    return d;
}
static __device__ __forceinline__ float u64_sum2(ull v) {
    float lo, hi;
    asm("mov.b64 {%0,%1}, %2;" : "=f"(lo), "=f"(hi) : "l"(v));
    return lo + hi;
}

// ---------------------------------------------------------------------------
// K1: segment sums. 512 threads = 4 independent row-groups of 128, each with
// its own 20KB smem replica -> RMW chain depth 1 per row. Partials to global.
// ---------------------------------------------------------------------------
__global__ __launch_bounds__(512) void k_segsum(const float4* __restrict__ E4,
                                                const int* __restrict__ labels,
                                                int nrows) {
    extern __shared__ float4 sm4[];            // [4][NC][D4]
    __shared__ int scnt[NC];
    const int g = threadIdx.x >> 7;            // group 0..3
    const int t = threadIdx.x & 127;           // float4 column
    float4* rep = sm4 + g * (NC * D4);

    if (threadIdx.x < NC) scnt[threadIdx.x] = 0;
#pragma unroll
    for (int c = 0; c < NC; c++) rep[c * D4 + t] = make_float4(0.f, 0.f, 0.f, 0.f);
    __syncthreads();

    const int  gid    = blockIdx.x * 4 + g;
    const long stride = (long)SEG_GROUPS * 4;
    for (long r0 = (long)gid * 4; r0 < nrows; r0 += stride) {
        if (r0 + 4 <= nrows) {
            const int4 lab4 = *(const int4*)(labels + r0);
            float4 v0 = E4[(size_t)(r0 + 0) * D4 + t];
            float4 v1 = E4[(size_t)(r0 + 1) * D4 + t];
            float4 v2 = E4[(size_t)(r0 + 2) * D4 + t];
            float4 v3 = E4[(size_t)(r0 + 3) * D4 + t];
            if (t == 0) {
                atomicAdd(&scnt[lab4.x], 1); atomicAdd(&scnt[lab4.y], 1);
                atomicAdd(&scnt[lab4.z], 1); atomicAdd(&scnt[lab4.w], 1);
            }
            float4* p;
            p = &rep[lab4.x * D4 + t];
            { float4 a = *p; a.x += v0.x; a.y += v0.y; a.z += v0.z; a.w += v0.w; *p = a; }
            p = &rep[lab4.y * D4 + t];
            { float4 a = *p; a.x += v1.x; a.y += v1.y; a.z += v1.z; a.w += v1.w; *p = a; }
            p = &rep[lab4.z * D4 + t];
            { float4 a = *p; a.x += v2.x; a.y += v2.y; a.z += v2.z; a.w += v2.w; *p = a; }
            p = &rep[lab4.w * D4 + t];
            { float4 a = *p; a.x += v3.x; a.y += v3.y; a.z += v3.z; a.w += v3.w; *p = a; }
        } else {
            for (int j = 0; j < 4 && r0 + j < nrows; j++) {
                int lj = labels[r0 + j];
                float4 v = E4[(size_t)(r0 + j) * D4 + t];
                if (t == 0) atomicAdd(&scnt[lj], 1);
                float4* p = &rep[lj * D4 + t];
                float4 a = *p; a.x += v.x; a.y += v.y; a.z += v.z; a.w += v.w; *p = a;
            }
        }
    }
    __syncthreads();

    for (int i = threadIdx.x; i < NC * D4; i += 512) {
        float4 a = sm4[i];
        float4 b = sm4[NC * D4 + i];
        float4 c = sm4[2 * NC * D4 + i];
        float4 d = sm4[3 * NC * D4 + i];
        a.x += b.x + c.x + d.x;
        a.y += b.y + c.y + d.y;
        a.z += b.z + c.z + d.z;
        a.w += b.w + c.w + d.w;
        g_part4[blockIdx.x * (NC * D4) + i] = a;
    }
    if (threadIdx.x < NC)
        g_cnt_part[blockIdx.x * NC + threadIdx.x] = scnt[threadIdx.x];
}

// ---------------------------------------------------------------------------
// K2: reduce partials -> g_sums4. grid 40 x 128: 4 threads per f4 element.
// ---------------------------------------------------------------------------
__global__ __launch_bounds__(128) void k_reduce() {
    const int i  = blockIdx.x * 32 + (threadIdx.x >> 2);   // f4 element 0..1279
    const int ps = threadIdx.x & 3;
    float4 acc = make_float4(0.f, 0.f, 0.f, 0.f);
#pragma unroll 8
    for (int p = ps; p < SEG_BLOCKS; p += 4) {
        float4 v = g_part4[p * (NC * D4) + i];
        acc.x += v.x; acc.y += v.y; acc.z += v.z; acc.w += v.w;
    }
#pragma unroll
    for (int st = 1; st <= 2; st <<= 1) {
        acc.x += __shfl_xor_sync(0xFFFFFFFFu, acc.x, st);
        acc.y += __shfl_xor_sync(0xFFFFFFFFu, acc.y, st);
        acc.z += __shfl_xor_sync(0xFFFFFFFFu, acc.z, st);
        acc.w += __shfl_xor_sync(0xFFFFFFFFu, acc.w, st);
    }
    if (ps == 0) g_sums4[i] = acc;
}

// ---------------------------------------------------------------------------
// K3: counts -> prototypes -> ||p||^2 ; also zero g_loss for this replay.
// ---------------------------------------------------------------------------
__global__ __launch_bounds__(512) void k_proto() {
    __shared__ float sinv[NC];
    const int tid = threadIdx.x, lane = tid & 31, w = tid >> 5;
    if (w < NC) {
        int s = 0;
        for (int p = lane; p < SEG_BLOCKS; p += 32) s += g_cnt_part[p * NC + w];
#pragma unroll
        for (int st = 16; st >= 1; st >>= 1) s += __shfl_xor_sync(0xFFFFFFFFu, s, st);
        if (lane == 0) sinv[w] = 1.0f / (float)s;
    }
    if (tid == 0) g_loss = 0.f;
    __syncthreads();
    const float* gs = (const float*)g_sums4;
    float*       gp = (float*)g_proto4;
#pragma unroll
    for (int c = 0; c < NC; c++) gp[c * DD + tid] = gs[c * DD + tid] * sinv[c];
    __syncthreads();
    if (w < NC) {
        const float* p = gp + w * DD;
        float acc = 0.f;
        for (int j = lane; j < DD; j += 32) acc = fmaf(p[j], p[j], acc);
#pragma unroll
        for (int st = 16; st >= 1; st >>= 1) acc += __shfl_xor_sync(0xFFFFFFFFu, acc, st);
        if (lane == 0) g_sqp[w] = acc;
    }
}

// ---------------------------------------------------------------------------
// K4 helpers. ALL intra-group shuffles use the 4-lane group mask so that
// divergence BETWEEN groups of one warp (tail block) cannot deadlock.
// ---------------------------------------------------------------------------
static __device__ __forceinline__ float row_epi(const float* dotf, float sqf,
                                                int row, int lab, bool valid,
                                                const float* __restrict__ ssqp,
                                                float* __restrict__ out,
                                                int cg, unsigned gmask) {
    float sqe = sqf;
    sqe += __shfl_xor_sync(gmask, sqe, 1);
    sqe += __shfl_xor_sync(gmask, sqe, 2);
    float l[NC];
    float m = -1e30f, lsel = 0.f;
#pragma unroll
    for (int c = 0; c < NC; c++) {
        float d = dotf[c];
        d += __shfl_xor_sync(gmask, d, 1);
        d += __shfl_xor_sync(gmask, d, 2);
        float d2 = sqe + ssqp[c] - 2.0f * d;
        float lg = -fmaxf(d2, 0.0f);
        l[c] = lg;
        m = fmaxf(m, lg);
        if (c == lab) lsel = lg;
    }
    float se = 0.f;
#pragma unroll
    for (int c = 0; c < NC; c++) se += __expf(l[c] - m);
    if (cg == 0 && valid) {
        float* o = out + 1 + (size_t)row * NC;
#pragma unroll
        for (int c = 0; c < NC; c++) o[c] = l[c];
    }
    return (cg == 0 && valid) ? (m + __logf(se) - lsel) : 0.f;
}

// Scalar path for tail rows. Row is pre-clamped; all 4 lanes of the group run.
static __device__ __forceinline__ float row_scalar(const float4* __restrict__ E4,
                                                   const float4* __restrict__ sp,
                                                   const float* __restrict__ ssqp,
                                                   int lab, float* __restrict__ out,
                                                   int row, bool valid,
                                                   int cg, unsigned gmask) {
    float dot[NC];
#pragma unroll
    for (int c = 0; c < NC; c++) dot[c] = 0.f;
    float sqf = 0.f;
    for (int t = cg; t < D4; t += 4) {
        float4 e = E4[(size_t)row * D4 + t];
        sqf += e.x * e.x + e.y * e.y + e.z * e.z + e.w * e.w;
#pragma unroll
        for (int c = 0; c < NC; c++) {
            float4 p = sp[c * D4 + t];
            dot[c] += e.x * p.x + e.y * p.y + e.z * p.z + e.w * p.w;
        }
    }
    return row_epi(dot, sqf, row, lab, valid, ssqp, out, cg, gmask);
}

// ---------------------------------------------------------------------------
// K4: logits + log-softmax + loss. 3 rows per 4-lane group, <=128 regs ->
// 4 blocks/SM. Rotate-prefetch: next iter's loads issue before current FMAs.
// ---------------------------------------------------------------------------
__global__ __launch_bounds__(128, 4) void k_logits(const float4* __restrict__ E4,
                                                   const int* __restrict__ labels,
                                                   float* __restrict__ out,
                                                   int nrows) {
    __shared__ float4 sp[NC * D4];   // 20 KB prototypes
    __shared__ float  ssqp[NC];
    __shared__ float  sloss;

    for (int i = threadIdx.x; i < NC * D4; i += 128) sp[i] = g_proto4[i];
    if (threadIdx.x < NC) ssqp[threadIdx.x] = g_sqp[threadIdx.x];
    if (threadIdx.x == 0) sloss = 0.f;
    __syncthreads();

    const int warp = threadIdx.x >> 5;
    const int lane = threadIdx.x & 31;
    const int cg   = lane & 3;
    const int grp  = lane >> 2;
    const unsigned gmask = 0xFu << (grp * 4);
    const int r0   = blockIdx.x * 96 + warp * 24 + grp * 3;

    float lvsum = 0.f;

    if (r0 + 3 <= nrows) {     // uniform within the 4-lane group
        const ulonglong2* __restrict__ Ep =
            (const ulonglong2*)E4 + (size_t)r0 * D4;
        const ulonglong2* __restrict__ Pp = (const ulonglong2*)sp;

        ull dot0[NC], dot1[NC], dot2[NC];
#pragma unroll
        for (int c = 0; c < NC; c++) { dot0[c] = 0; dot1[c] = 0; dot2[c] = 0; }
        ull sq0 = 0, sq1 = 0, sq2 = 0;

        ulonglong2 v0 = Ep[cg];
        ulonglong2 v1 = Ep[cg + D4];
        ulonglong2 v2 = Ep[cg + 2 * D4];

#pragma unroll 4
        for (int k = 0; k < 32; k++) {
            const int idx  = k * 4 + cg;
            const int pidx = (idx + 4) & 127;        // wrap avoids OOB at k=31
            ulonglong2 n0 = Ep[pidx];
            ulonglong2 n1 = Ep[pidx + D4];
            ulonglong2 n2 = Ep[pidx + 2 * D4];

            sq0 = fma2(v0.x, v0.x, sq0); sq0 = fma2(v0.y, v0.y, sq0);
            sq1 = fma2(v1.x, v1.x, sq1); sq1 = fma2(v1.y, v1.y, sq1);
            sq2 = fma2(v2.x, v2.x, sq2); sq2 = fma2(v2.y, v2.y, sq2);
#pragma unroll
            for (int c = 0; c < NC; c++) {
                ulonglong2 p = Pp[c * D4 + idx];
                dot0[c] = fma2(v0.x, p.x, dot0[c]); dot0[c] = fma2(v0.y, p.y, dot0[c]);
                dot1[c] = fma2(v1.x, p.x, dot1[c]); dot1[c] = fma2(v1.y, p.y, dot1[c]);
                dot2[c] = fma2(v2.x, p.x, dot2[c]); dot2[c] = fma2(v2.y, p.y, dot2[c]);
            }
            v0 = n0; v1 = n1; v2 = n2;
        }

        const int l0 = labels[r0], l1 = labels[r0 + 1], l2 = labels[r0 + 2];
        float df[NC];
#pragma unroll
        for (int c = 0; c < NC; c++) df[c] = u64_sum2(dot0[c]);
        lvsum += row_epi(df, u64_sum2(sq0), r0 + 0, l0, true, ssqp, out, cg, gmask);
#pragma unroll
        for (int c = 0; c < NC; c++) df[c] = u64_sum2(dot1[c]);
        lvsum += row_epi(df, u64_sum2(sq1), r0 + 1, l1, true, ssqp, out, cg, gmask);
#pragma unroll
        for (int c = 0; c < NC; c++) df[c] = u64_sum2(dot2[c]);
        lvsum += row_epi(df, u64_sum2(sq2), r0 + 2, l2, true, ssqp, out, cg, gmask);
    } else {
        // Tail: run all 3 rows unconditionally with clamped indices so every
        // lane of the group participates in every shuffle.
        for (int j = 0; j < 3; j++) {
            const int  row   = r0 + j;
            const bool valid = (row < nrows);
            const int  rowc  = valid ? row : (nrows > 0 ? nrows - 1 : 0);
            const int  lab   = labels[rowc];
            lvsum += row_scalar(E4, sp, ssqp, lab, out, rowc, valid, cg, gmask);
        }
    }

    // Reconverged: full-warp reduction is safe here.
#pragma unroll
    for (int st = 16; st >= 1; st >>= 1)
        lvsum += __shfl_xor_sync(0xFFFFFFFFu, lvsum, st);
    if (lane == 0) atomicAdd(&sloss, lvsum);
    __syncthreads();
    if (threadIdx.x == 0) atomicAdd(&g_loss, sloss);
}

// ---------------------------------------------------------------------------
// K5: finalize loss
// ---------------------------------------------------------------------------
__global__ void k_final(float* __restrict__ out, int nrows) {
    out[0] = g_loss * (1.0f / (float)nrows);
}

extern "C" void kernel_launch(void* const* d_in, const int* in_sizes, int n_in,
                              void* d_out, int out_size) {
    const float* E      = (const float*)d_in[0];
    const int*   labels = (const int*)d_in[1];
    float*       out    = (float*)d_out;
    const int nrows = in_sizes[1];   // 131072

    cudaFuncSetAttribute(k_segsum, cudaFuncAttributeMaxDynamicSharedMemorySize,
                         SEG_SMEM);

    k_segsum<<<SEG_BLOCKS, 512, SEG_SMEM>>>((const float4*)E, labels, nrows);
    k_reduce<<<40, 128>>>();
    k_proto<<<1, 512>>>();
    k_logits<<<(nrows + 95) / 96, 128>>>((const float4*)E, labels, out, nrows);
    k_final<<<1, 1>>>(out, nrows);
}